// round 14
// baseline (speedup 1.0000x reference)
#include <cuda_runtime.h>
#include <cuda_bf16.h>
#include <cstdint>
#include <math.h>

#define N_BATCH 4096
#define D_FEAT  64
#define KDIM    256                       // packed [u, -2mu, a, b]
#define TILE    128
#define NBLK    (N_BATCH / TILE)          // 32
#define NPAIRS  (NBLK * (NBLK + 1) / 2)   // 528
#define NCHUNK  8                         // k chunks of 32
#define STAGES  4                         // 8 chunks -> exactly 2 phases/stage/item
#define PFD     2
#define NTHR    256
#define GRID    304                       // <= 152 SMs x 2; work-steal, no residency req

// ---- scratch (static device globals; no allocation allowed) ----
// A: [blk 32][chunk 8][rb 8][ks 2][lane 32][slot 4][half 2] bf16
__device__ __align__(256) __nv_bfloat16 g_VA[N_BATCH * KDIM];
// B (k rotated by 128): [blk 32][chunk 8][nb 16][lane 32][slot 4][half 2] bf16
__device__ __align__(256) __nv_bfloat16 g_VB[N_BATCH * KDIM];
__device__ __align__(256) float g_C[N_BATCH];
__device__ __align__(256) float g_P[N_BATCH];
__device__ __align__(256) float g_RP[N_BATCH];
__device__ double g_acc[2];
__device__ unsigned g_done;
__device__ unsigned g_next;

// ---- smem layout ----
#define STAGE_BYTES 16384
#define MB_BASE   (STAGES * STAGE_BYTES)     // 65536; 8 mbarriers (128 B)
#define OFF_ROWD0 (MB_BASE + 128)            // 128 float4
#define OFF_COLD0 (OFF_ROWD0 + 2048)
#define OFF_ROWD1 (OFF_COLD0 + 2048)
#define OFF_COLD1 (OFF_ROWD1 + 2048)
#define OFF_REDP  (OFF_COLD1 + 2048)
#define OFF_REDN  (OFF_REDP + 40)
#define OFF_IDX   (OFF_REDN + 40)
#define SM_BYTES  (OFF_IDX + 32)

// ---------------------------------------------------------------
__device__ __forceinline__ uint32_t smem_u32(const void* p) {
    uint32_t a;
    asm("{ .reg .u64 t; cvta.to.shared.u64 t, %1; cvt.u32.u64 %0, t; }" : "=r"(a) : "l"(p));
    return a;
}
__device__ __forceinline__ void cp16(uint32_t dst, const void* src) {
    asm volatile("cp.async.cg.shared.global [%0], [%1], 16;" :: "r"(dst), "l"(src));
}
#define MB_INIT(mb, c)  asm volatile("mbarrier.init.shared.b64 [%0], %1;" :: "r"(mb), "r"((uint32_t)(c)) : "memory")
#define MB_ARRIVE(mb)   asm volatile("mbarrier.arrive.shared.b64 _, [%0];" :: "r"(mb) : "memory")
#define CP_MB_ARRIVE(mb) asm volatile("cp.async.mbarrier.arrive.noinc.shared.b64 [%0];" :: "r"(mb) : "memory")

__device__ __forceinline__ void mbwait(uint32_t mb, uint32_t phase) {
    asm volatile(
        "{\n\t.reg .pred P;\n\t"
        "LW_%=:\n\t"
        "mbarrier.try_wait.parity.shared.b64 P, [%0], %1;\n\t"
        "@!P bra LW_%=;\n\t}"
        :: "r"(mb), "r"(phase) : "memory");
}
__device__ __forceinline__ uint32_t mb_full(uint32_t smb, int s)  { return smb + MB_BASE + s * 16; }
__device__ __forceinline__ uint32_t mb_empty(uint32_t smb, int s) { return smb + MB_BASE + s * 16 + 8; }

// ---------------------------------------------------------------
__device__ __forceinline__ uint32_t pack_bf162(float lo, float hi) {
    __nv_bfloat16 l = __float2bfloat16_rn(lo), h = __float2bfloat16_rn(hi);
    uint16_t lb, hb;
    memcpy(&lb, &l, 2); memcpy(&hb, &h, 2);
    return (uint32_t)lb | ((uint32_t)hb << 16);
}

__global__ void __launch_bounds__(256)
precompute_kernel(const float* __restrict__ mu, const float* __restrict__ var) {
    int tid = threadIdx.x;
    int wid = tid >> 5;
    int lane = tid & 31;
    int row = blockIdx.x * 8 + wid;          // 512*8 = 4096 exactly
    if (blockIdx.x == 0 && tid == 0) { g_acc[0] = 0.0; g_acc[1] = 0.0; }

    float2 vv = ((const float2*)var)[row * 32 + lane];
    float2 mv = ((const float2*)mu )[row * 32 + lane];
    float iv0 = 1.0f / vv.x, iv1 = 1.0f / vv.y;

    uint32_t wv[4];
    wv[0] = pack_bf162(vv.x + mv.x * mv.x, vv.y + mv.y * mv.y);  // u
    wv[1] = pack_bf162(-2.0f * mv.x,       -2.0f * mv.y);        // -2mu
    wv[2] = pack_bf162(iv0,                iv1);                 // a
    wv[3] = pack_bf162(mv.x * iv0,         mv.y * iv1);          // b

    int b = row >> 7, r = row & 127;
    int rb = r >> 4, ri = r & 15;
    int nb = r >> 3, ji = r & 7;
    uint32_t* VA = (uint32_t*)g_VA;
    uint32_t* VB = (uint32_t*)g_VB;
    #pragma unroll
    for (int g = 0; g < 4; g++) {
        int k0 = g * 64 + 2 * lane;
        int c  = k0 >> 5, kc = k0 & 31;
        int ks = kc >> 4, kk = kc & 15;
        int cB = (c + 4) & 7;
        int laneA = (ri & 7) * 4 + ((kk >> 1) & 3);
        int slotA = (ri >> 3) + 2 * (kk >> 3);
        size_t wA = (((((size_t)b * 8 + c) * 8 + rb) * 2 + ks) * 32 + laneA) * 4 + slotA;
        VA[wA] = wv[g];
        int laneB = ji * 4 + ((kk >> 1) & 3);
        int slotB = ks * 2 + (kk >> 3);
        size_t wB = ((((size_t)b * 8 + cB) * 16 + nb) * 32 + laneB) * 4 + slotB;
        VB[wB] = wv[g];
    }

    float sc = mv.x * mv.x * iv0 + mv.y * mv.y * iv1;
    float sp = vv.x * vv.y;
    #pragma unroll
    for (int off = 16; off; off >>= 1) {
        sc += __shfl_xor_sync(0xffffffffu, sc, off);
        sp *= __shfl_xor_sync(0xffffffffu, sp, off);
    }
    if (lane == 0) {
        g_C[row]  = sc;
        g_P[row]  = sp;
        g_RP[row] = 1.0f / (sp + 1e-8f);
    }
}

// ---------------------------------------------------------------
__device__ __forceinline__ void issue_chunk(uint32_t smbase, int stage,
                                            int bi, int bj, int c, int tid) {
    const __nv_bfloat16* srcA = g_VA + ((size_t)bi * 8 + c) * 4096;
    const __nv_bfloat16* srcB = g_VB + ((size_t)bj * 8 + c) * 4096;
    uint32_t dst = smbase + stage * STAGE_BYTES;
    #pragma unroll
    for (int it = 0; it < 2; it++) {
        int idx = tid + it * NTHR;
        cp16(dst + idx * 16,        srcA + idx * 8);
        cp16(dst + 8192 + idx * 16, srcB + idx * 8);
    }
}

__device__ __forceinline__ void lda(const uint4* pA, int wm, int ks, int lane,
                                    uint32_t a[4][4]) {
    #pragma unroll
    for (int tm = 0; tm < 4; tm++) {
        const uint4 v = pA[(((wm * 4 + tm) * 2 + ks) * 32 + lane)];
        a[tm][0] = v.x; a[tm][1] = v.y; a[tm][2] = v.z; a[tm][3] = v.w;
    }
}
__device__ __forceinline__ void ldb4(const uint4* pB, int wn, int lane,
                                     uint32_t b[4][4]) {
    #pragma unroll
    for (int tn = 0; tn < 4; tn++) {
        const uint4 v = pB[((wn * 4 + tn) * 32 + lane)];
        b[tn][0] = v.x; b[tn][1] = v.y; b[tn][2] = v.z; b[tn][3] = v.w;
    }
}

__device__ __forceinline__ void ep_elem(float S, float4 R, float4 C, int r, int cl,
                                        bool diag, float& pos, float& neg) {
    float hs = fmaf(0.125f, S, R.x) + fmaf(R.z, C.x, fmaf(R.y, C.y, C.z));
    float th;
    asm("tanh.approx.f32 %0, %1;" : "=f"(th) : "f"(hs));
    if (!diag || (r < cl)) {
        float t = 1.0f + th;
        if (__float_as_int(R.w) == __float_as_int(C.w)) pos += t; else neg += t;
    }
}

__device__ __forceinline__ void decode_pair(int idx, int& bi, int& bj) {
    int t = idx, b = 0;
    while (t >= NBLK - b) { t -= NBLK - b; b++; }
    bi = b; bj = b + t;
}

extern __shared__ __align__(16) float sm_dyn[];

__global__ void __launch_bounds__(NTHR, 2)
pair_kernel(const int* __restrict__ labels, float* __restrict__ out) {
    float* sm = sm_dyn;
    uint32_t smb = smem_u32(sm);
    int tid  = threadIdx.x;
    int wid  = tid >> 5;
    int lane = tid & 31;
    int wm = wid & 1;        // 64-row half
    int wn = wid >> 1;       // 32-col quarter

    // ---- init mbarriers ----
    if (tid == 0) {
        #pragma unroll
        for (int s = 0; s < STAGES; s++) {
            MB_INIT(mb_full(smb, s), NTHR);
            MB_INIT(mb_empty(smb, s), NTHR);
        }
    }
    __syncthreads();

    int idx = blockIdx.x;          // static first item (GRID < NPAIRS)
    int bi, bj;
    decode_pair(idx, bi, bj);

    // first item prologue (wait empty parity 1: passes at init)
    #pragma unroll
    for (int c = 0; c < PFD; c++) {
        mbwait(mb_empty(smb, c), 1u);
        issue_chunk(smb, c, bi, bj, c, tid);
        CP_MB_ARRIVE(mb_full(smb, c));
    }

    float* redp = (float*)((char*)sm + OFF_REDP);
    float* redn = (float*)((char*)sm + OFF_REDN);
    int* sidx = (int*)((char*)sm + OFF_IDX);
    int itpar = 0;

    for (;;) {
        // epilogue constants for this item (double-buffered)
        float4* rowd = (float4*)((char*)sm + (itpar ? OFF_ROWD1 : OFF_ROWD0));
        float4* cold = (float4*)((char*)sm + (itpar ? OFF_COLD1 : OFF_COLD0));
        if (tid < 128) {
            int gi = bi * TILE + tid, gj = bj * TILE + tid;
            rowd[tid] = make_float4(0.125f * g_C[gi], g_P[gi], g_RP[gi],
                                    __int_as_float(labels[gi]));
            cold[tid] = make_float4(0.125f * g_P[gj], 0.125f * g_RP[gj],
                                    0.125f * g_C[gj] - 16.0f, __int_as_float(labels[gj]));
        }

        float acc[4][4][4];
        #pragma unroll
        for (int i = 0; i < 4; i++)
            #pragma unroll
            for (int j = 0; j < 4; j++)
                #pragma unroll
                for (int k = 0; k < 4; k++) acc[i][j][k] = 0.0f;

        // ---- mainloop: 8 chunks, item-invariant parities ----
        #pragma unroll
        for (int c = 0; c < NCHUNK; c++) {
            const int s = c & 3;
            if (c + PFD < NCHUNK) {
                const int c2 = c + PFD, s2 = c2 & 3;
                mbwait(mb_empty(smb, s2), (c2 < STAGES) ? 1u : 0u);
                issue_chunk(smb, s2, bi, bj, c2, tid);
                CP_MB_ARRIVE(mb_full(smb, s2));
            }
            mbwait(mb_full(smb, s), (uint32_t)((c >> 2) & 1));

            const uint4* pA = (const uint4*)((const char*)sm + s * STAGE_BYTES);
            const uint4* pB = (const uint4*)((const char*)sm + s * STAGE_BYTES + 8192);
            uint32_t B[4][4];
            ldb4(pB, wn, lane, B);
            #pragma unroll
            for (int ks = 0; ks < 2; ks++) {
                uint32_t A[4][4];
                lda(pA, wm, ks, lane, A);
                #pragma unroll
                for (int tm = 0; tm < 4; tm++)
                    #pragma unroll
                    for (int tn = 0; tn < 4; tn++)
                        asm volatile(
                            "mma.sync.aligned.m16n8k16.row.col.f32.bf16.bf16.f32 "
                            "{%0,%1,%2,%3},{%4,%5,%6,%7},{%8,%9},{%0,%1,%2,%3};"
                            : "+f"(acc[tm][tn][0]), "+f"(acc[tm][tn][1]),
                              "+f"(acc[tm][tn][2]), "+f"(acc[tm][tn][3])
                            : "r"(A[tm][0]), "r"(A[tm][1]), "r"(A[tm][2]), "r"(A[tm][3]),
                              "r"(B[tn][ks * 2]), "r"(B[tn][ks * 2 + 1]));
            }
            MB_ARRIVE(mb_empty(smb, s));
        }

        // ---- steal next item; publish + order rowd/cold ----
        if (tid == 0) *sidx = GRID + (int)atomicAdd(&g_next, 1u);
        __syncthreads();
        int nidx = *sidx;
        bool more = (nidx < NPAIRS);
        int nbi = 0, nbj = 0;
        if (more) {
            decode_pair(nidx, nbi, nbj);
            // issue next item's prologue BEFORE epilogue -> ramp hidden
            #pragma unroll
            for (int c = 0; c < PFD; c++) {
                mbwait(mb_empty(smb, c), 1u);
                issue_chunk(smb, c, nbi, nbj, c, tid);
                CP_MB_ARRIVE(mb_full(smb, c));
            }
        }

        // ---- epilogue ----
        bool diag = (bi == bj);
        float pos = 0.0f, neg = 0.0f;
        int r0 = wm * 64 + (lane >> 2);
        int c0 = wn * 32 + 2 * (lane & 3);
        #pragma unroll
        for (int tm = 0; tm < 4; tm++) {
            int r1 = r0 + tm * 16, r2 = r1 + 8;
            float4 R1 = rowd[r1], R2 = rowd[r2];
            #pragma unroll
            for (int tn = 0; tn < 4; tn++) {
                int ca = c0 + tn * 8;
                float4 C1 = cold[ca], C2 = cold[ca + 1];
                ep_elem(acc[tm][tn][0], R1, C1, r1, ca,     diag, pos, neg);
                ep_elem(acc[tm][tn][1], R1, C2, r1, ca + 1, diag, pos, neg);
                ep_elem(acc[tm][tn][2], R2, C1, r2, ca,     diag, pos, neg);
                ep_elem(acc[tm][tn][3], R2, C2, r2, ca + 1, diag, pos, neg);
            }
        }
        #pragma unroll
        for (int off = 16; off; off >>= 1) {
            pos += __shfl_xor_sync(0xffffffffu, pos, off);
            neg += __shfl_xor_sync(0xffffffffu, neg, off);
        }
        if (lane == 0) { redp[wid] = pos; redn[wid] = neg; }
        __syncthreads();
        if (tid == 0) {
            float p = 0.0f, n = 0.0f;
            #pragma unroll
            for (int i = 0; i < 8; i++) { p += redp[i]; n += redn[i]; }
            atomicAdd(&g_acc[0], (double)p);
            atomicAdd(&g_acc[1], (double)n);
        }

        if (!more) break;
        idx = nidx; bi = nbi; bj = nbj; itpar ^= 1;
    }

    // ---- finish: last CTA finalizes + resets counters for graph replay ----
    if (tid == 0) {
        __threadfence();
        unsigned v = atomicAdd(&g_done, 1u);
        if (v == GRID - 1) {
            double P = g_acc[0], N = g_acc[1];
            const double invN2 = 1.0 / ((double)N_BATCH * (double)N_BATCH);
            out[0] = (float)(P * invN2);
            out[1] = (float)(N * invN2);
            out[2] = (float)P;
            out[3] = (float)N;
            g_done = 0; g_next = 0;
        }
    }
}

// ---------------------------------------------------------------
extern "C" void kernel_launch(void* const* d_in, const int* in_sizes, int n_in,
                              void* d_out, int out_size) {
    const float* mu     = (const float*)d_in[0];
    const float* var    = (const float*)d_in[1];
    const int*   labels = (const int*)d_in[2];
    float* out = (float*)d_out;

    cudaFuncSetAttribute(pair_kernel, cudaFuncAttributeMaxDynamicSharedMemorySize, SM_BYTES);

    precompute_kernel<<<512, 256>>>(mu, var);
    pair_kernel<<<GRID, NTHR, SM_BYTES>>>(labels, out);
}

// round 15
// speedup vs baseline: 1.3661x; 1.3661x over previous
#include <cuda_runtime.h>
#include <cuda_bf16.h>
#include <cstdint>
#include <math.h>

#define N_BATCH 4096
#define D_FEAT  64
#define KDIM    256                       // packed [u, -2mu, a, b]
#define TILE    128
#define NBLK    (N_BATCH / TILE)          // 32
#define NPAIRS  (NBLK * (NBLK + 1) / 2)   // 528
#define NCHUNK  8                         // k chunks of 32
#define STAGES  3
#define PFD     2
#define NTHR    256

// ---- scratch (static device globals; no allocation allowed) ----
// bf16 fragment-permuted operands for mma.sync.m16n8k16
// A: [blk 32][chunk 8][rb 8][ks 2][lane 32][slot 4][half 2] bf16
__device__ __align__(256) __nv_bfloat16 g_VA[N_BATCH * KDIM];
// B (k rotated by 128): [blk 32][chunk 8][nb 16][lane 32][slot 4][half 2] bf16
__device__ __align__(256) __nv_bfloat16 g_VB[N_BATCH * KDIM];
__device__ __align__(256) float g_C[N_BATCH];
__device__ __align__(256) float g_P[N_BATCH];
__device__ __align__(256) float g_RP[N_BATCH];
__device__ double g_acc[2];
__device__ unsigned g_done;

// ---- smem: 3 stages x 16KB + mbarriers + dedicated epilogue region ----
#define STAGE_BYTES 16384
#define MB_BASE   (STAGES * STAGE_BYTES)   // 49152
#define OFF_ROWD  (MB_BASE + 64)           // 128 float4
#define OFF_COLD  (OFF_ROWD + 2048)        // 128 float4
#define OFF_REDP  (OFF_COLD + 2048)
#define OFF_REDN  (OFF_REDP + 40)
#define SM_BYTES  (OFF_REDN + 64)

// ---------------------------------------------------------------
__device__ __forceinline__ uint32_t smem_u32(const void* p) {
    uint32_t a;
    asm("{ .reg .u64 t; cvta.to.shared.u64 t, %1; cvt.u32.u64 %0, t; }" : "=r"(a) : "l"(p));
    return a;
}
__device__ __forceinline__ void cp16(uint32_t dst, const void* src) {
    asm volatile("cp.async.cg.shared.global [%0], [%1], 16;" :: "r"(dst), "l"(src));
}
#define MB_INIT(mb, c)  asm volatile("mbarrier.init.shared.b64 [%0], %1;" :: "r"(mb), "r"((uint32_t)(c)) : "memory")
#define MB_ARRIVE(mb)   asm volatile("mbarrier.arrive.shared.b64 _, [%0];" :: "r"(mb) : "memory")
#define CP_MB_ARRIVE(mb) asm volatile("cp.async.mbarrier.arrive.noinc.shared.b64 [%0];" :: "r"(mb) : "memory")

__device__ __forceinline__ void mbwait(uint32_t mb, uint32_t phase) {
    asm volatile(
        "{\n\t.reg .pred P;\n\t"
        "LW_%=:\n\t"
        "mbarrier.try_wait.parity.shared.b64 P, [%0], %1;\n\t"
        "@!P bra LW_%=;\n\t}"
        :: "r"(mb), "r"(phase) : "memory");
}
__device__ __forceinline__ uint32_t mb_full(uint32_t smb, int s)  { return smb + MB_BASE + s * 16; }
__device__ __forceinline__ uint32_t mb_empty(uint32_t smb, int s) { return smb + MB_BASE + s * 16 + 8; }

// ---------------------------------------------------------------
// Fat precompute: 512 CTAs x 256 threads, one warp per row.
// Each lane handles features d0=2*lane, d0+1 -> all stores are 32-bit words.
__device__ __forceinline__ uint32_t pack_bf162(float lo, float hi) {
    __nv_bfloat16 l = __float2bfloat16_rn(lo), h = __float2bfloat16_rn(hi);
    uint16_t lb, hb;
    memcpy(&lb, &l, 2); memcpy(&hb, &h, 2);
    return (uint32_t)lb | ((uint32_t)hb << 16);
}

__global__ void __launch_bounds__(256)
precompute_kernel(const float* __restrict__ mu, const float* __restrict__ var) {
    int tid = threadIdx.x;
    int wid = tid >> 5;
    int lane = tid & 31;
    int row = blockIdx.x * 8 + wid;          // 512*8 = 4096 exactly
    if (blockIdx.x == 0 && tid == 0) { g_acc[0] = 0.0; g_acc[1] = 0.0; }

    float2 vv = ((const float2*)var)[row * 32 + lane];
    float2 mv = ((const float2*)mu )[row * 32 + lane];
    float iv0 = 1.0f / vv.x, iv1 = 1.0f / vv.y;

    // group g: values at k = g*64 + 2*lane (+1)
    uint32_t wv[4];
    wv[0] = pack_bf162(vv.x + mv.x * mv.x, vv.y + mv.y * mv.y);  // u
    wv[1] = pack_bf162(-2.0f * mv.x,       -2.0f * mv.y);        // -2mu
    wv[2] = pack_bf162(iv0,                iv1);                 // a
    wv[3] = pack_bf162(mv.x * iv0,         mv.y * iv1);          // b

    int b = row >> 7, r = row & 127;
    int rb = r >> 4, ri = r & 15;
    int nb = r >> 3, ji = r & 7;
    uint32_t* VA = (uint32_t*)g_VA;
    uint32_t* VB = (uint32_t*)g_VB;
    #pragma unroll
    for (int g = 0; g < 4; g++) {
        int k0 = g * 64 + 2 * lane;          // even
        int c  = k0 >> 5, kc = k0 & 31;
        int ks = kc >> 4, kk = kc & 15;
        int cB = (c + 4) & 7;                // J-side rotation baked into B layout
        int laneA = (ri & 7) * 4 + ((kk >> 1) & 3);
        int slotA = (ri >> 3) + 2 * (kk >> 3);
        size_t wA = (((((size_t)b * 8 + c) * 8 + rb) * 2 + ks) * 32 + laneA) * 4 + slotA;
        VA[wA] = wv[g];
        int laneB = ji * 4 + ((kk >> 1) & 3);
        int slotB = ks * 2 + (kk >> 3);
        size_t wB = ((((size_t)b * 8 + cB) * 16 + nb) * 32 + laneB) * 4 + slotB;
        VB[wB] = wv[g];
    }

    float sc = mv.x * mv.x * iv0 + mv.y * mv.y * iv1;
    float sp = vv.x * vv.y;
    #pragma unroll
    for (int off = 16; off; off >>= 1) {
        sc += __shfl_xor_sync(0xffffffffu, sc, off);
        sp *= __shfl_xor_sync(0xffffffffu, sp, off);
    }
    if (lane == 0) {
        g_C[row]  = sc;
        g_P[row]  = sp;
        g_RP[row] = 1.0f / (sp + 1e-8f);
    }
    // PDL: allow the dependent pair_kernel to start launching; its
    // cudaGridDependencySynchronize() still orders all our stores first.
#if __CUDA_ARCH__ >= 900
    cudaTriggerProgrammaticLaunchCompletion();
#endif
}

// ---------------------------------------------------------------
// One chunk = 16KB: A 8KB + B 8KB. 256 threads x 2 x cp16 = 16KB.
__device__ __forceinline__ void issue_chunk(uint32_t smbase, int stage,
                                            int bi, int bj, int c, int tid) {
    const __nv_bfloat16* srcA = g_VA + ((size_t)bi * 8 + c) * 4096;
    const __nv_bfloat16* srcB = g_VB + ((size_t)bj * 8 + c) * 4096;
    uint32_t dst = smbase + stage * STAGE_BYTES;
    #pragma unroll
    for (int it = 0; it < 2; it++) {
        int idx = tid + it * NTHR;
        cp16(dst + idx * 16,        srcA + idx * 8);
        cp16(dst + 8192 + idx * 16, srcB + idx * 8);
    }
}

// fragment loads (uint4 units within a stage)
__device__ __forceinline__ void lda(const uint4* pA, int wm, int ks, int lane,
                                    uint32_t a[4][4]) {
    #pragma unroll
    for (int tm = 0; tm < 4; tm++) {
        const uint4 v = pA[(((wm * 4 + tm) * 2 + ks) * 32 + lane)];
        a[tm][0] = v.x; a[tm][1] = v.y; a[tm][2] = v.z; a[tm][3] = v.w;
    }
}
__device__ __forceinline__ void ldb4(const uint4* pB, int wn, int lane,
                                     uint32_t b[4][4]) {
    #pragma unroll
    for (int tn = 0; tn < 4; tn++) {
        const uint4 v = pB[((wn * 4 + tn) * 32 + lane)];
        b[tn][0] = v.x; b[tn][1] = v.y; b[tn][2] = v.z; b[tn][3] = v.w;
    }
}

// contribution = 2*sigmoid(sym) = 1 + tanh(sym/2); R/C carry 0.125-folded constants
__device__ __forceinline__ void ep_elem(float S, float4 R, float4 C, int r, int cl,
                                        bool diag, float& pos, float& neg) {
    float hs = fmaf(0.125f, S, R.x) + fmaf(R.z, C.x, fmaf(R.y, C.y, C.z));
    float th;
    asm("tanh.approx.f32 %0, %1;" : "=f"(th) : "f"(hs));
    if (!diag || (r < cl)) {
        float t = 1.0f + th;
        if (__float_as_int(R.w) == __float_as_int(C.w)) pos += t; else neg += t;
    }
}

extern __shared__ __align__(16) float sm_dyn[];

__global__ void __launch_bounds__(NTHR, 2)
pair_kernel(const int* __restrict__ labels, float* __restrict__ out) {
    float* sm = sm_dyn;
    uint32_t smb = smem_u32(sm);
    int tid  = threadIdx.x;
    int wid  = tid >> 5;
    int lane = tid & 31;
    int wm = wid & 1;        // 64-row half
    int wn = wid >> 1;       // 32-col quarter

    int t = blockIdx.x, bi = 0;
    while (t >= NBLK - bi) { t -= NBLK - bi; bi++; }
    int bj = bi + t;

    float acc[4][4][4];
    #pragma unroll
    for (int i = 0; i < 4; i++)
        #pragma unroll
        for (int j = 0; j < 4; j++)
            #pragma unroll
            for (int k = 0; k < 4; k++) acc[i][j][k] = 0.0f;

    // ---- init mbarriers (no global reads yet — overlaps upstream tail) ----
    if (tid == 0) {
        #pragma unroll
        for (int s = 0; s < STAGES; s++) {
            MB_INIT(mb_full(smb, s), NTHR);
            MB_INIT(mb_empty(smb, s), NTHR);
        }
    }
    __syncthreads();

    // PDL: wait for precompute's stores to be visible before any global read.
#if __CUDA_ARCH__ >= 900
    cudaGridDependencySynchronize();
#endif

    // epilogue constants into dedicated smem region, hidden under mainloop
    float4* rowd = (float4*)((char*)sm + OFF_ROWD);
    float4* cold = (float4*)((char*)sm + OFF_COLD);
    if (tid < 128) {
        int gi = bi * TILE + tid, gj = bj * TILE + tid;
        rowd[tid] = make_float4(0.125f * g_C[gi], g_P[gi], g_RP[gi],
                                __int_as_float(labels[gi]));
        cold[tid] = make_float4(0.125f * g_P[gj], 0.125f * g_RP[gj],
                                0.125f * g_C[gj] - 16.0f, __int_as_float(labels[gj]));
    }

    // prologue: issue chunks 0..PFD-1
    #pragma unroll
    for (int c = 0; c < PFD; c++) {
        issue_chunk(smb, c, bi, bj, c, tid);
        CP_MB_ARRIVE(mb_full(smb, c));
    }

    #pragma unroll
    for (int c = 0; c < NCHUNK; c++) {
        const int s = c % STAGES;
        if (c + PFD < NCHUNK) {
            const int c2 = c + PFD, s2 = c2 % STAGES, k2 = c2 / STAGES;
            if (k2 > 0) mbwait(mb_empty(smb, s2), (uint32_t)((k2 - 1) & 1));
            issue_chunk(smb, s2, bi, bj, c2, tid);
            CP_MB_ARRIVE(mb_full(smb, s2));
        }
        mbwait(mb_full(smb, s), (uint32_t)((c / STAGES) & 1));

        const uint4* pA = (const uint4*)((const char*)sm + s * STAGE_BYTES);
        const uint4* pB = (const uint4*)((const char*)sm + s * STAGE_BYTES + 8192);
        uint32_t B[4][4];
        ldb4(pB, wn, lane, B);
        #pragma unroll
        for (int ks = 0; ks < 2; ks++) {
            uint32_t A[4][4];
            lda(pA, wm, ks, lane, A);
            #pragma unroll
            for (int tm = 0; tm < 4; tm++)
                #pragma unroll
                for (int tn = 0; tn < 4; tn++)
                    asm volatile(
                        "mma.sync.aligned.m16n8k16.row.col.f32.bf16.bf16.f32 "
                        "{%0,%1,%2,%3},{%4,%5,%6,%7},{%8,%9},{%0,%1,%2,%3};"
                        : "+f"(acc[tm][tn][0]), "+f"(acc[tm][tn][1]),
                          "+f"(acc[tm][tn][2]), "+f"(acc[tm][tn][3])
                        : "r"(A[tm][0]), "r"(A[tm][1]), "r"(A[tm][2]), "r"(A[tm][3]),
                          "r"(B[tn][ks * 2]), "r"(B[tn][ks * 2 + 1]));
        }
        MB_ARRIVE(mb_empty(smb, s));
    }

    // ---- epilogue ----
    __syncthreads();
    bool diag = (bi == bj);
    float pos = 0.0f, neg = 0.0f;
    int r0 = wm * 64 + (lane >> 2);
    int c0 = wn * 32 + 2 * (lane & 3);
    #pragma unroll
    for (int tm = 0; tm < 4; tm++) {
        int r1 = r0 + tm * 16, r2 = r1 + 8;
        float4 R1 = rowd[r1], R2 = rowd[r2];
        #pragma unroll
        for (int tn = 0; tn < 4; tn++) {
            int ca = c0 + tn * 8;
            float4 C1 = cold[ca], C2 = cold[ca + 1];
            ep_elem(acc[tm][tn][0], R1, C1, r1, ca,     diag, pos, neg);
            ep_elem(acc[tm][tn][1], R1, C2, r1, ca + 1, diag, pos, neg);
            ep_elem(acc[tm][tn][2], R2, C1, r2, ca,     diag, pos, neg);
            ep_elem(acc[tm][tn][3], R2, C2, r2, ca + 1, diag, pos, neg);
        }
    }

    #pragma unroll
    for (int off = 16; off; off >>= 1) {
        pos += __shfl_xor_sync(0xffffffffu, pos, off);
        neg += __shfl_xor_sync(0xffffffffu, neg, off);
    }
    float* redp = (float*)((char*)sm + OFF_REDP);
    float* redn = (float*)((char*)sm + OFF_REDN);
    if (lane == 0) { redp[wid] = pos; redn[wid] = neg; }
    __syncthreads();
    if (tid == 0) {
        float p = 0.0f, n = 0.0f;
        #pragma unroll
        for (int i = 0; i < 8; i++) { p += redp[i]; n += redn[i]; }
        atomicAdd(&g_acc[0], (double)p);
        atomicAdd(&g_acc[1], (double)n);
        __threadfence();
        unsigned v = atomicAdd(&g_done, 1u);
        if (v == NPAIRS - 1) {               // last CTA finalizes
            g_done = 0;
            double P = g_acc[0], N = g_acc[1];
            const double invN2 = 1.0 / ((double)N_BATCH * (double)N_BATCH);
            out[0] = (float)(P * invN2);
            out[1] = (float)(N * invN2);
            out[2] = (float)P;
            out[3] = (float)N;
        }
    }
}

// ---------------------------------------------------------------
extern "C" void kernel_launch(void* const* d_in, const int* in_sizes, int n_in,
                              void* d_out, int out_size) {
    const float* mu     = (const float*)d_in[0];
    const float* var    = (const float*)d_in[1];
    const int*   labels = (const int*)d_in[2];
    float* out = (float*)d_out;

    cudaFuncSetAttribute(pair_kernel, cudaFuncAttributeMaxDynamicSharedMemorySize, SM_BYTES);

    precompute_kernel<<<512, 256>>>(mu, var);

    // PDL launch of pair_kernel; fall back to a plain launch on any failure.
    cudaLaunchConfig_t cfg = {};
    cfg.gridDim = dim3(NPAIRS, 1, 1);
    cfg.blockDim = dim3(NTHR, 1, 1);
    cfg.dynamicSmemBytes = SM_BYTES;
    cudaLaunchAttribute attrs[1];
    attrs[0].id = cudaLaunchAttributeProgrammaticStreamSerialization;
    attrs[0].val.programmaticStreamSerializationAllowed = 1;
    cfg.attrs = attrs;
    cfg.numAttrs = 1;
    cudaError_t err = cudaLaunchKernelEx(&cfg, pair_kernel, labels, out);
    if (err != cudaSuccess) {
        (void)cudaGetLastError();           // clear sticky error
        pair_kernel<<<NPAIRS, NTHR, SM_BYTES>>>(labels, out);
    }
}